// round 2
// baseline (speedup 1.0000x reference)
#include <cuda_runtime.h>
#include <cuda_bf16.h>

#define SEQ 2048
#define DIM 2048
#define NH 32
#define NKV 8
#define HD 64

// ---------------- scratch (static device globals; no runtime alloc) ----------
__device__ float g_q[SEQ * NH * HD];     // [s][h][d]
__device__ float g_k[SEQ * NKV * HD];    // [s][kv][d]
__device__ float g_v[SEQ * NKV * HD];    // [s][kv][d]
__device__ float g_gate[SEQ * DIM];      // x @ wg.T (pre-sigmoid)
__device__ float g_att[SEQ * DIM];       // gated attention output

// ---------------- SGEMM: C[M][N] = A[M][K] * B[N][K]^T ----------------------
// BM=BN=128, BK=8, TM=TN=8, 256 threads
__global__ void __launch_bounds__(256) sgemm_tn(const float* __restrict__ A,
                                                const float* __restrict__ B,
                                                float* __restrict__ C,
                                                int M, int N, int K)
{
    __shared__ float As[8][128];
    __shared__ float Bs[8][128];

    const int tid = threadIdx.x;
    const int ty  = tid >> 4;         // 0..15
    const int tx  = tid & 15;         // 0..15
    const int lr  = tid >> 1;         // 0..127
    const int lc  = (tid & 1) * 4;    // 0 or 4

    const float* Ab = A + (blockIdx.y * 128 + lr) * (long)K + lc;
    const float* Bb = B + (blockIdx.x * 128 + lr) * (long)K + lc;

    float acc[8][8];
    #pragma unroll
    for (int i = 0; i < 8; i++)
        #pragma unroll
        for (int j = 0; j < 8; j++) acc[i][j] = 0.f;

    for (int kb = 0; kb < K; kb += 8) {
        float4 a = *(const float4*)(Ab + kb);
        float4 b = *(const float4*)(Bb + kb);
        As[lc + 0][lr] = a.x; As[lc + 1][lr] = a.y;
        As[lc + 2][lr] = a.z; As[lc + 3][lr] = a.w;
        Bs[lc + 0][lr] = b.x; Bs[lc + 1][lr] = b.y;
        Bs[lc + 2][lr] = b.z; Bs[lc + 3][lr] = b.w;
        __syncthreads();

        #pragma unroll
        for (int kk = 0; kk < 8; kk++) {
            float4 a0 = *(const float4*)&As[kk][ty * 8];
            float4 a1 = *(const float4*)&As[kk][ty * 8 + 4];
            float4 b0 = *(const float4*)&Bs[kk][tx * 8];
            float4 b1 = *(const float4*)&Bs[kk][tx * 8 + 4];
            float ra[8] = {a0.x, a0.y, a0.z, a0.w, a1.x, a1.y, a1.z, a1.w};
            float rb[8] = {b0.x, b0.y, b0.z, b0.w, b1.x, b1.y, b1.z, b1.w};
            #pragma unroll
            for (int i = 0; i < 8; i++)
                #pragma unroll
                for (int j = 0; j < 8; j++)
                    acc[i][j] += ra[i] * rb[j];
        }
        __syncthreads();
    }

    #pragma unroll
    for (int i = 0; i < 8; i++) {
        float* Cr = C + (blockIdx.y * 128 + ty * 8 + i) * (long)N + blockIdx.x * 128 + tx * 8;
        *(float4*)Cr       = make_float4(acc[i][0], acc[i][1], acc[i][2], acc[i][3]);
        *(float4*)(Cr + 4) = make_float4(acc[i][4], acc[i][5], acc[i][6], acc[i][7]);
    }
}

// ---------------- fused RoPE + RMSNorm (one warp per (s,head) row) ----------
__global__ void rope_rmsnorm(float* __restrict__ t, const float* __restrict__ cosb,
                             const float* __restrict__ sinb, const float* __restrict__ w,
                             int nheads, int nrows)
{
    int row  = blockIdx.x * 8 + (threadIdx.x >> 5);
    if (row >= nrows) return;
    int lane = threadIdx.x & 31;
    int s    = row / nheads;

    float* p = t + row * HD;
    float2 xv = ((float2*)p)[lane];
    float c  = cosb[s * (HD / 2) + lane];
    float sn = sinb[s * (HD / 2) + lane];
    float orr = xv.x * c - xv.y * sn;
    float oi  = xv.x * sn + xv.y * c;

    float ss = orr * orr + oi * oi;
    #pragma unroll
    for (int o = 16; o; o >>= 1) ss += __shfl_xor_sync(0xffffffffu, ss, o);
    float inv = rsqrtf(ss * (1.f / HD) + 1e-6f);

    float2 wv = ((const float2*)w)[lane];
    ((float2*)p)[lane] = make_float2(orr * inv * wv.x, oi * inv * wv.y);
}

// ---------------- flash attention 64x64 + fused sigmoid gate ----------------
// grid (SEQ/64, NH), 256 threads as 16x16; thread (ty,tx) owns rows ty*4..+3,
// cols/dims tx*4..+3.
__global__ void __launch_bounds__(256) attn_kernel(const float* __restrict__ q,
                                                   const float* __restrict__ k,
                                                   const float* __restrict__ v,
                                                   const float* __restrict__ gate,
                                                   float* __restrict__ o)
{
    __shared__ float Qst[64 * 64];   // Qst[d*64 + r]  (d-major, pre-scaled)
    __shared__ float Kst[64 * 64];   // Kst[d*64 + c]; aliased as Ps[r*64+c]
    __shared__ float Vs[64 * 64];    // Vs[c*64 + d]
    float* Ps = Kst;

    const int qb  = blockIdx.x;
    const int h   = blockIdx.y;
    const int kvh = h >> 2;              // NREP = 4
    const int tid = threadIdx.x;
    const int ty  = tid >> 4, tx = tid & 15;
    const int qi0 = qb * 64;

    // load Q tile transposed, folding in softmax scale 1/sqrt(64)
    {
        int r  = tid >> 2;
        int d0 = (tid & 3) * 16;
        const float* qp = q + (qi0 + r) * (NH * HD) + h * HD + d0;
        #pragma unroll
        for (int u = 0; u < 4; u++) {
            float4 t4 = *(const float4*)(qp + u * 4);
            Qst[(d0 + u * 4 + 0) * 64 + r] = t4.x * 0.125f;
            Qst[(d0 + u * 4 + 1) * 64 + r] = t4.y * 0.125f;
            Qst[(d0 + u * 4 + 2) * 64 + r] = t4.z * 0.125f;
            Qst[(d0 + u * 4 + 3) * 64 + r] = t4.w * 0.125f;
        }
    }

    float m_i[4], l_i[4], oacc[4][4];
    #pragma unroll
    for (int i = 0; i < 4; i++) {
        m_i[i] = -1e30f; l_i[i] = 0.f;
        #pragma unroll
        for (int j = 0; j < 4; j++) oacc[i][j] = 0.f;
    }

    for (int kb = 0; kb <= qb; kb++) {
        const int kj0 = kb * 64;
        __syncthreads();  // previous O-update done (and Q scatter on iter 0)

        // load K (transposed) and V tiles
        {
            int c  = tid >> 2;
            int d0 = (tid & 3) * 16;
            const float* kp = k + (kj0 + c) * (NKV * HD) + kvh * HD + d0;
            const float* vp = v + (kj0 + c) * (NKV * HD) + kvh * HD + d0;
            #pragma unroll
            for (int u = 0; u < 4; u++) {
                float4 t4 = *(const float4*)(kp + u * 4);
                Kst[(d0 + u * 4 + 0) * 64 + c] = t4.x;
                Kst[(d0 + u * 4 + 1) * 64 + c] = t4.y;
                Kst[(d0 + u * 4 + 2) * 64 + c] = t4.z;
                Kst[(d0 + u * 4 + 3) * 64 + c] = t4.w;
                *(float4*)&Vs[c * 64 + d0 + u * 4] = *(const float4*)(vp + u * 4);
            }
        }
        __syncthreads();

        // S = Q K^T (scaled already)
        float sc[4][4];
        #pragma unroll
        for (int i = 0; i < 4; i++)
            #pragma unroll
            for (int j = 0; j < 4; j++) sc[i][j] = 0.f;

        #pragma unroll 8
        for (int d = 0; d < 64; d++) {
            float4 qv = *(const float4*)&Qst[d * 64 + ty * 4];
            float4 kv = *(const float4*)&Kst[d * 64 + tx * 4];
            float ra[4] = {qv.x, qv.y, qv.z, qv.w};
            float rb[4] = {kv.x, kv.y, kv.z, kv.w};
            #pragma unroll
            for (int i = 0; i < 4; i++)
                #pragma unroll
                for (int j = 0; j < 4; j++)
                    sc[i][j] += ra[i] * rb[j];
        }

        if (kb == qb) {   // diagonal tile: causal mask
            #pragma unroll
            for (int i = 0; i < 4; i++)
                #pragma unroll
                for (int j = 0; j < 4; j++)
                    if (tx * 4 + j > ty * 4 + i) sc[i][j] = -1e30f;
        }

        // online softmax (row stats reduced over the 16-lane tx group)
        float alpha[4];
        #pragma unroll
        for (int i = 0; i < 4; i++) {
            float mt = fmaxf(fmaxf(sc[i][0], sc[i][1]), fmaxf(sc[i][2], sc[i][3]));
            #pragma unroll
            for (int off = 8; off; off >>= 1)
                mt = fmaxf(mt, __shfl_xor_sync(0xffffffffu, mt, off));
            float mn = fmaxf(m_i[i], mt);
            alpha[i] = __expf(m_i[i] - mn);
            m_i[i] = mn;
            float rs = 0.f;
            #pragma unroll
            for (int j = 0; j < 4; j++) {
                sc[i][j] = __expf(sc[i][j] - mn);
                rs += sc[i][j];
            }
            #pragma unroll
            for (int off = 8; off; off >>= 1)
                rs += __shfl_xor_sync(0xffffffffu, rs, off);
            l_i[i] = l_i[i] * alpha[i] + rs;
        }

        __syncthreads();  // all K reads done; Kst may be reused as Ps
        #pragma unroll
        for (int i = 0; i < 4; i++) {
            #pragma unroll
            for (int j = 0; j < 4; j++)
                Ps[(ty * 4 + i) * 64 + tx * 4 + j] = sc[i][j];
            #pragma unroll
            for (int jd = 0; jd < 4; jd++) oacc[i][jd] *= alpha[i];
        }
        __syncthreads();  // Ps visible

        // O += P V
        #pragma unroll 8
        for (int j = 0; j < 64; j++) {
            float4 vv = *(const float4*)&Vs[j * 64 + tx * 4];
            #pragma unroll
            for (int i = 0; i < 4; i++) {
                float p = Ps[(ty * 4 + i) * 64 + j];
                oacc[i][0] += p * vv.x;
                oacc[i][1] += p * vv.y;
                oacc[i][2] += p * vv.z;
                oacc[i][3] += p * vv.w;
            }
        }
    }

    // epilogue: normalize + fused sigmoid gate
    #pragma unroll
    for (int i = 0; i < 4; i++) {
        int row = qi0 + ty * 4 + i;
        float invl = 1.f / l_i[i];
        const float* gp = gate + row * DIM + h * HD + tx * 4;
        float4 g4 = *(const float4*)gp;
        float4 ov;
        ov.x = oacc[i][0] * invl * (1.f / (1.f + __expf(-g4.x)));
        ov.y = oacc[i][1] * invl * (1.f / (1.f + __expf(-g4.y)));
        ov.z = oacc[i][2] * invl * (1.f / (1.f + __expf(-g4.z)));
        ov.w = oacc[i][3] * invl * (1.f / (1.f + __expf(-g4.w)));
        *(float4*)(o + row * DIM + h * HD + tx * 4) = ov;
    }
}

// ---------------- launcher ---------------------------------------------------
extern "C" void kernel_launch(void* const* d_in, const int* in_sizes, int n_in,
                              void* d_out, int out_size)
{
    const float* x    = (const float*)d_in[0];
    const float* cosb = (const float*)d_in[1];
    const float* sinb = (const float*)d_in[2];
    const float* wq   = (const float*)d_in[3];
    const float* wk   = (const float*)d_in[4];
    const float* wv   = (const float*)d_in[5];
    const float* wo   = (const float*)d_in[6];
    const float* wg   = (const float*)d_in[7];
    const float* qn   = (const float*)d_in[8];
    const float* kn   = (const float*)d_in[9];
    float* out = (float*)d_out;

    float *qb, *kb, *vb, *gb, *ab;
    cudaGetSymbolAddress((void**)&qb, g_q);
    cudaGetSymbolAddress((void**)&kb, g_k);
    cudaGetSymbolAddress((void**)&vb, g_v);
    cudaGetSymbolAddress((void**)&gb, g_gate);
    cudaGetSymbolAddress((void**)&ab, g_att);

    // projections
    sgemm_tn<<<dim3(DIM / 128, SEQ / 128), 256>>>(x, wq, qb, SEQ, DIM, DIM);
    sgemm_tn<<<dim3((NKV * HD) / 128, SEQ / 128), 256>>>(x, wk, kb, SEQ, NKV * HD, DIM);
    sgemm_tn<<<dim3((NKV * HD) / 128, SEQ / 128), 256>>>(x, wv, vb, SEQ, NKV * HD, DIM);
    sgemm_tn<<<dim3(DIM / 128, SEQ / 128), 256>>>(x, wg, gb, SEQ, DIM, DIM);

    // RoPE + RMSNorm (q: 65536 rows, k: 16384 rows; 8 warps/block)
    rope_rmsnorm<<<(SEQ * NH) / 8, 256>>>(qb, cosb, sinb, qn, NH, SEQ * NH);
    rope_rmsnorm<<<(SEQ * NKV) / 8, 256>>>(kb, cosb, sinb, kn, NKV, SEQ * NKV);

    // causal GQA flash attention + fused sigmoid gate
    attn_kernel<<<dim3(SEQ / 64, NH), 256>>>(qb, kb, vb, gb, ab);

    // output projection
    sgemm_tn<<<dim3(DIM / 128, SEQ / 128), 256>>>(ab, wo, out, SEQ, DIM, DIM);
}

// round 4
// speedup vs baseline: 3.0392x; 3.0392x over previous
#include <cuda_runtime.h>
#include <cuda_bf16.h>
#include <cstdint>

#define SEQ 2048
#define DIM 2048
#define NH 32
#define NKV 8
#define HD 64

// ---------------- scratch (static device globals; no runtime alloc) ----------
__device__ float g_q[SEQ * NH * HD];     // [s][h][d]
__device__ float g_k[SEQ * NKV * HD];    // [s][kv][d]
__device__ float g_v[SEQ * NKV * HD];    // [s][kv][d]
__device__ float g_gate[SEQ * DIM];      // x @ wg.T (pre-sigmoid)
__device__ float g_att[SEQ * DIM];       // gated attention output

// ---------------- tf32 helpers ----------------------------------------------
__device__ __forceinline__ uint32_t f2tf32(float f) {
    uint32_t r;
    asm("cvt.rna.tf32.f32 %0, %1;" : "=r"(r) : "f"(f));
    return r;
}

__device__ __forceinline__ void mma_tf32(float c[4],
                                         uint32_t a0, uint32_t a1, uint32_t a2, uint32_t a3,
                                         uint32_t b0, uint32_t b1)
{
    asm volatile(
        "mma.sync.aligned.m16n8k8.row.col.f32.tf32.tf32.f32 "
        "{%0,%1,%2,%3}, {%4,%5,%6,%7}, {%8,%9}, {%0,%1,%2,%3};"
        : "+f"(c[0]), "+f"(c[1]), "+f"(c[2]), "+f"(c[3])
        : "r"(a0), "r"(a1), "r"(a2), "r"(a3), "r"(b0), "r"(b1));
}

// ---------------- tensor-core GEMM: C[M][N] = A[M][K] * B[N][K]^T -----------
// BM=BN=128, BK=16, 256 threads (8 warps 2x4), warp tile 64x32 via m16n8k8 tf32.
// smem row stride 20 words -> fragment LDS is fully bank-conflict-free.
__global__ void __launch_bounds__(256, 2) gemm_tf32(const float* __restrict__ A,
                                                    const float* __restrict__ B,
                                                    float* __restrict__ C,
                                                    int M, int N, int K)
{
    __shared__ uint32_t As[128][20];
    __shared__ uint32_t Bs[128][20];

    const int tid  = threadIdx.x;
    const int lane = tid & 31;
    const int warp = tid >> 5;
    const int wm   = warp & 1;    // 0..1  (64 rows each)
    const int wn   = warp >> 1;   // 0..3  (32 cols each)
    const int g    = lane >> 2;   // 0..7
    const int tg   = lane & 3;    // 0..3

    const int lrow = tid >> 1;           // 0..127
    const int lcol = (tid & 1) * 8;      // 0 or 8

    const float* Ag = A + (blockIdx.y * 128 + lrow) * (long)K + lcol;
    const float* Bg = B + (blockIdx.x * 128 + lrow) * (long)K + lcol;

    float c[4][4][4];
    #pragma unroll
    for (int mt = 0; mt < 4; mt++)
        #pragma unroll
        for (int nt = 0; nt < 4; nt++)
            #pragma unroll
            for (int r = 0; r < 4; r++) c[mt][nt][r] = 0.f;

    // prefetch first tile
    float4 pa0 = *(const float4*)(Ag + 0);
    float4 pa1 = *(const float4*)(Ag + 4);
    float4 pb0 = *(const float4*)(Bg + 0);
    float4 pb1 = *(const float4*)(Bg + 4);

    for (int kb = 0; kb < K; kb += 16) {
        __syncthreads();   // previous compute finished
        As[lrow][lcol + 0] = f2tf32(pa0.x); As[lrow][lcol + 1] = f2tf32(pa0.y);
        As[lrow][lcol + 2] = f2tf32(pa0.z); As[lrow][lcol + 3] = f2tf32(pa0.w);
        As[lrow][lcol + 4] = f2tf32(pa1.x); As[lrow][lcol + 5] = f2tf32(pa1.y);
        As[lrow][lcol + 6] = f2tf32(pa1.z); As[lrow][lcol + 7] = f2tf32(pa1.w);
        Bs[lrow][lcol + 0] = f2tf32(pb0.x); Bs[lrow][lcol + 1] = f2tf32(pb0.y);
        Bs[lrow][lcol + 2] = f2tf32(pb0.z); Bs[lrow][lcol + 3] = f2tf32(pb0.w);
        Bs[lrow][lcol + 4] = f2tf32(pb1.x); Bs[lrow][lcol + 5] = f2tf32(pb1.y);
        Bs[lrow][lcol + 6] = f2tf32(pb1.z); Bs[lrow][lcol + 7] = f2tf32(pb1.w);
        __syncthreads();

        if (kb + 16 < K) {   // prefetch next tile (hides GMEM latency under mma)
            pa0 = *(const float4*)(Ag + kb + 16);
            pa1 = *(const float4*)(Ag + kb + 20);
            pb0 = *(const float4*)(Bg + kb + 16);
            pb1 = *(const float4*)(Bg + kb + 20);
        }

        #pragma unroll
        for (int ks = 0; ks < 16; ks += 8) {
            uint32_t af[4][4];
            uint32_t bf[4][2];
            #pragma unroll
            for (int mt = 0; mt < 4; mt++) {
                int r = wm * 64 + mt * 16 + g;
                af[mt][0] = As[r    ][ks + tg    ];
                af[mt][1] = As[r + 8][ks + tg    ];
                af[mt][2] = As[r    ][ks + tg + 4];
                af[mt][3] = As[r + 8][ks + tg + 4];
            }
            #pragma unroll
            for (int nt = 0; nt < 4; nt++) {
                int r = wn * 32 + nt * 8 + g;
                bf[nt][0] = Bs[r][ks + tg    ];
                bf[nt][1] = Bs[r][ks + tg + 4];
            }
            #pragma unroll
            for (int mt = 0; mt < 4; mt++)
                #pragma unroll
                for (int nt = 0; nt < 4; nt++)
                    mma_tf32(c[mt][nt], af[mt][0], af[mt][1], af[mt][2], af[mt][3],
                             bf[nt][0], bf[nt][1]);
        }
    }

    // epilogue
    #pragma unroll
    for (int mt = 0; mt < 4; mt++) {
        int row = blockIdx.y * 128 + wm * 64 + mt * 16 + g;
        #pragma unroll
        for (int nt = 0; nt < 4; nt++) {
            int col = blockIdx.x * 128 + wn * 32 + nt * 8 + 2 * tg;
            *(float2*)(C + (long)row * N + col)       = make_float2(c[mt][nt][0], c[mt][nt][1]);
            *(float2*)(C + (long)(row + 8) * N + col) = make_float2(c[mt][nt][2], c[mt][nt][3]);
        }
    }
}

// ---------------- fused RoPE + RMSNorm (one warp per (s,head) row) ----------
__global__ void rope_rmsnorm(float* __restrict__ t, const float* __restrict__ cosb,
                             const float* __restrict__ sinb, const float* __restrict__ w,
                             int nheads, int nrows)
{
    int row  = blockIdx.x * 8 + (threadIdx.x >> 5);
    if (row >= nrows) return;
    int lane = threadIdx.x & 31;
    int s    = row / nheads;

    float* p = t + row * HD;
    float2 xv = ((float2*)p)[lane];
    float c  = cosb[s * (HD / 2) + lane];
    float sn = sinb[s * (HD / 2) + lane];
    float orr = xv.x * c - xv.y * sn;
    float oi  = xv.x * sn + xv.y * c;

    float ss = orr * orr + oi * oi;
    #pragma unroll
    for (int o = 16; o; o >>= 1) ss += __shfl_xor_sync(0xffffffffu, ss, o);
    float inv = rsqrtf(ss * (1.f / HD) + 1e-6f);

    float2 wv = ((const float2*)w)[lane];
    ((float2*)p)[lane] = make_float2(orr * inv * wv.x, oi * inv * wv.y);
}

// ---------------- flash attention 64x64 + fused sigmoid gate ----------------
__global__ void __launch_bounds__(256) attn_kernel(const float* __restrict__ q,
                                                   const float* __restrict__ k,
                                                   const float* __restrict__ v,
                                                   const float* __restrict__ gate,
                                                   float* __restrict__ o)
{
    __shared__ float Qst[64 * 64];   // Qst[d*64 + r]  (d-major, pre-scaled)
    __shared__ float Kst[64 * 64];   // Kst[d*64 + c]; aliased as Ps[r*64+c]
    __shared__ float Vs[64 * 64];    // Vs[c*64 + d]
    float* Ps = Kst;

    const int qb  = blockIdx.x;
    const int h   = blockIdx.y;
    const int kvh = h >> 2;              // NREP = 4
    const int tid = threadIdx.x;
    const int ty  = tid >> 4, tx = tid & 15;
    const int qi0 = qb * 64;

    {
        int r  = tid >> 2;
        int d0 = (tid & 3) * 16;
        const float* qp = q + (qi0 + r) * (NH * HD) + h * HD + d0;
        #pragma unroll
        for (int u = 0; u < 4; u++) {
            float4 t4 = *(const float4*)(qp + u * 4);
            Qst[(d0 + u * 4 + 0) * 64 + r] = t4.x * 0.125f;
            Qst[(d0 + u * 4 + 1) * 64 + r] = t4.y * 0.125f;
            Qst[(d0 + u * 4 + 2) * 64 + r] = t4.z * 0.125f;
            Qst[(d0 + u * 4 + 3) * 64 + r] = t4.w * 0.125f;
        }
    }

    float m_i[4], l_i[4], oacc[4][4];
    #pragma unroll
    for (int i = 0; i < 4; i++) {
        m_i[i] = -1e30f; l_i[i] = 0.f;
        #pragma unroll
        for (int j = 0; j < 4; j++) oacc[i][j] = 0.f;
    }

    for (int kb = 0; kb <= qb; kb++) {
        const int kj0 = kb * 64;
        __syncthreads();

        {
            int c  = tid >> 2;
            int d0 = (tid & 3) * 16;
            const float* kp = k + (kj0 + c) * (NKV * HD) + kvh * HD + d0;
            const float* vp = v + (kj0 + c) * (NKV * HD) + kvh * HD + d0;
            #pragma unroll
            for (int u = 0; u < 4; u++) {
                float4 t4 = *(const float4*)(kp + u * 4);
                Kst[(d0 + u * 4 + 0) * 64 + c] = t4.x;
                Kst[(d0 + u * 4 + 1) * 64 + c] = t4.y;
                Kst[(d0 + u * 4 + 2) * 64 + c] = t4.z;
                Kst[(d0 + u * 4 + 3) * 64 + c] = t4.w;
                *(float4*)&Vs[c * 64 + d0 + u * 4] = *(const float4*)(vp + u * 4);
            }
        }
        __syncthreads();

        float sc[4][4];
        #pragma unroll
        for (int i = 0; i < 4; i++)
            #pragma unroll
            for (int j = 0; j < 4; j++) sc[i][j] = 0.f;

        #pragma unroll 8
        for (int d = 0; d < 64; d++) {
            float4 qv = *(const float4*)&Qst[d * 64 + ty * 4];
            float4 kv = *(const float4*)&Kst[d * 64 + tx * 4];
            float ra[4] = {qv.x, qv.y, qv.z, qv.w};
            float rb[4] = {kv.x, kv.y, kv.z, kv.w};
            #pragma unroll
            for (int i = 0; i < 4; i++)
                #pragma unroll
                for (int j = 0; j < 4; j++)
                    sc[i][j] += ra[i] * rb[j];
        }

        if (kb == qb) {
            #pragma unroll
            for (int i = 0; i < 4; i++)
                #pragma unroll
                for (int j = 0; j < 4; j++)
                    if (tx * 4 + j > ty * 4 + i) sc[i][j] = -1e30f;
        }

        float alpha[4];
        #pragma unroll
        for (int i = 0; i < 4; i++) {
            float mt = fmaxf(fmaxf(sc[i][0], sc[i][1]), fmaxf(sc[i][2], sc[i][3]));
            #pragma unroll
            for (int off = 8; off; off >>= 1)
                mt = fmaxf(mt, __shfl_xor_sync(0xffffffffu, mt, off));
            float mn = fmaxf(m_i[i], mt);
            alpha[i] = __expf(m_i[i] - mn);
            m_i[i] = mn;
            float rs = 0.f;
            #pragma unroll
            for (int j = 0; j < 4; j++) {
                sc[i][j] = __expf(sc[i][j] - mn);
                rs += sc[i][j];
            }
            #pragma unroll
            for (int off = 8; off; off >>= 1)
                rs += __shfl_xor_sync(0xffffffffu, rs, off);
            l_i[i] = l_i[i] * alpha[i] + rs;
        }

        __syncthreads();
        #pragma unroll
        for (int i = 0; i < 4; i++) {
            #pragma unroll
            for (int j = 0; j < 4; j++)
                Ps[(ty * 4 + i) * 64 + tx * 4 + j] = sc[i][j];
            #pragma unroll
            for (int jd = 0; jd < 4; jd++) oacc[i][jd] *= alpha[i];
        }
        __syncthreads();

        #pragma unroll 8
        for (int j = 0; j < 64; j++) {
            float4 vv = *(const float4*)&Vs[j * 64 + tx * 4];
            #pragma unroll
            for (int i = 0; i < 4; i++) {
                float p = Ps[(ty * 4 + i) * 64 + j];
                oacc[i][0] += p * vv.x;
                oacc[i][1] += p * vv.y;
                oacc[i][2] += p * vv.z;
                oacc[i][3] += p * vv.w;
            }
        }
    }

    #pragma unroll
    for (int i = 0; i < 4; i++) {
        int row = qi0 + ty * 4 + i;
        float invl = 1.f / l_i[i];
        const float* gp = gate + row * DIM + h * HD + tx * 4;
        float4 g4 = *(const float4*)gp;
        float4 ov;
        ov.x = oacc[i][0] * invl * (1.f / (1.f + __expf(-g4.x)));
        ov.y = oacc[i][1] * invl * (1.f / (1.f + __expf(-g4.y)));
        ov.z = oacc[i][2] * invl * (1.f / (1.f + __expf(-g4.z)));
        ov.w = oacc[i][3] * invl * (1.f / (1.f + __expf(-g4.w)));
        *(float4*)(o + row * DIM + h * HD + tx * 4) = ov;
    }
}

// ---------------- launcher ---------------------------------------------------
extern "C" void kernel_launch(void* const* d_in, const int* in_sizes, int n_in,
                              void* d_out, int out_size)
{
    const float* x    = (const float*)d_in[0];
    const float* cosb = (const float*)d_in[1];
    const float* sinb = (const float*)d_in[2];
    const float* wq   = (const float*)d_in[3];
    const float* wk   = (const float*)d_in[4];
    const float* wv   = (const float*)d_in[5];
    const float* wo   = (const float*)d_in[6];
    const float* wg   = (const float*)d_in[7];
    const float* qn   = (const float*)d_in[8];
    const float* kn   = (const float*)d_in[9];
    float* out = (float*)d_out;

    float *qb, *kb, *vb, *gb, *ab;
    cudaGetSymbolAddress((void**)&qb, g_q);
    cudaGetSymbolAddress((void**)&kb, g_k);
    cudaGetSymbolAddress((void**)&vb, g_v);
    cudaGetSymbolAddress((void**)&gb, g_gate);
    cudaGetSymbolAddress((void**)&ab, g_att);

    // projections (tensor cores, tf32)
    gemm_tf32<<<dim3(DIM / 128, SEQ / 128), 256>>>(x, wq, qb, SEQ, DIM, DIM);
    gemm_tf32<<<dim3((NKV * HD) / 128, SEQ / 128), 256>>>(x, wk, kb, SEQ, NKV * HD, DIM);
    gemm_tf32<<<dim3((NKV * HD) / 128, SEQ / 128), 256>>>(x, wv, vb, SEQ, NKV * HD, DIM);
    gemm_tf32<<<dim3(DIM / 128, SEQ / 128), 256>>>(x, wg, gb, SEQ, DIM, DIM);

    // RoPE + RMSNorm
    rope_rmsnorm<<<(SEQ * NH) / 8, 256>>>(qb, cosb, sinb, qn, NH, SEQ * NH);
    rope_rmsnorm<<<(SEQ * NKV) / 8, 256>>>(kb, cosb, sinb, kn, NKV, SEQ * NKV);

    // causal GQA flash attention + fused sigmoid gate
    attn_kernel<<<dim3(SEQ / 64, NH), 256>>>(qb, kb, vb, gb, ab);

    // output projection (tensor cores, tf32)
    gemm_tf32<<<dim3(DIM / 128, SEQ / 128), 256>>>(ab, wo, out, SEQ, DIM, DIM);
}

// round 6
// speedup vs baseline: 3.9189x; 1.2894x over previous
#include <cuda_runtime.h>
#include <cuda_bf16.h>
#include <cstdint>

#define SEQ 2048
#define DIM 2048
#define NH 32
#define NKV 8
#define HD 64

// ---------------- scratch (static device globals; no runtime alloc) ----------
__device__ float g_q[SEQ * NH * HD];     // [s][h][d]
__device__ float g_k[SEQ * NKV * HD];    // [s][kv][d]
__device__ float g_v[SEQ * NKV * HD];    // [s][kv][d]
__device__ float g_gate[SEQ * DIM];      // x @ wg.T (pre-sigmoid)
__device__ float g_att[SEQ * DIM];       // gated attention output

// ---------------- tf32 helpers ----------------------------------------------
__device__ __forceinline__ uint32_t f2tf32(float f) {
    uint32_t r;
    asm("cvt.rna.tf32.f32 %0, %1;" : "=r"(r) : "f"(f));
    return r;
}

__device__ __forceinline__ void mma_tf32(float c[4],
                                         uint32_t a0, uint32_t a1, uint32_t a2, uint32_t a3,
                                         uint32_t b0, uint32_t b1)
{
    asm volatile(
        "mma.sync.aligned.m16n8k8.row.col.f32.tf32.tf32.f32 "
        "{%0,%1,%2,%3}, {%4,%5,%6,%7}, {%8,%9}, {%0,%1,%2,%3};"
        : "+f"(c[0]), "+f"(c[1]), "+f"(c[2]), "+f"(c[3])
        : "r"(a0), "r"(a1), "r"(a2), "r"(a3), "r"(b0), "r"(b1));
}

// ---------------- tensor-core GEMM: C[M][N] = A[M][K] * B[N][K]^T -----------
__global__ void __launch_bounds__(256, 2) gemm_tf32(const float* __restrict__ A,
                                                    const float* __restrict__ B,
                                                    float* __restrict__ C,
                                                    int M, int N, int K)
{
    __shared__ uint32_t As[128][20];
    __shared__ uint32_t Bs[128][20];

    const int tid  = threadIdx.x;
    const int lane = tid & 31;
    const int warp = tid >> 5;
    const int wm   = warp & 1;
    const int wn   = warp >> 1;
    const int g    = lane >> 2;
    const int tg   = lane & 3;

    const int lrow = tid >> 1;
    const int lcol = (tid & 1) * 8;

    const float* Ag = A + (blockIdx.y * 128 + lrow) * (long)K + lcol;
    const float* Bg = B + (blockIdx.x * 128 + lrow) * (long)K + lcol;

    float c[4][4][4];
    #pragma unroll
    for (int mt = 0; mt < 4; mt++)
        #pragma unroll
        for (int nt = 0; nt < 4; nt++)
            #pragma unroll
            for (int r = 0; r < 4; r++) c[mt][nt][r] = 0.f;

    float4 pa0 = *(const float4*)(Ag + 0);
    float4 pa1 = *(const float4*)(Ag + 4);
    float4 pb0 = *(const float4*)(Bg + 0);
    float4 pb1 = *(const float4*)(Bg + 4);

    for (int kb = 0; kb < K; kb += 16) {
        __syncthreads();
        As[lrow][lcol + 0] = f2tf32(pa0.x); As[lrow][lcol + 1] = f2tf32(pa0.y);
        As[lrow][lcol + 2] = f2tf32(pa0.z); As[lrow][lcol + 3] = f2tf32(pa0.w);
        As[lrow][lcol + 4] = f2tf32(pa1.x); As[lrow][lcol + 5] = f2tf32(pa1.y);
        As[lrow][lcol + 6] = f2tf32(pa1.z); As[lrow][lcol + 7] = f2tf32(pa1.w);
        Bs[lrow][lcol + 0] = f2tf32(pb0.x); Bs[lrow][lcol + 1] = f2tf32(pb0.y);
        Bs[lrow][lcol + 2] = f2tf32(pb0.z); Bs[lrow][lcol + 3] = f2tf32(pb0.w);
        Bs[lrow][lcol + 4] = f2tf32(pb1.x); Bs[lrow][lcol + 5] = f2tf32(pb1.y);
        Bs[lrow][lcol + 6] = f2tf32(pb1.z); Bs[lrow][lcol + 7] = f2tf32(pb1.w);
        __syncthreads();

        if (kb + 16 < K) {
            pa0 = *(const float4*)(Ag + kb + 16);
            pa1 = *(const float4*)(Ag + kb + 20);
            pb0 = *(const float4*)(Bg + kb + 16);
            pb1 = *(const float4*)(Bg + kb + 20);
        }

        #pragma unroll
        for (int ks = 0; ks < 16; ks += 8) {
            uint32_t af[4][4];
            uint32_t bf[4][2];
            #pragma unroll
            for (int mt = 0; mt < 4; mt++) {
                int r = wm * 64 + mt * 16 + g;
                af[mt][0] = As[r    ][ks + tg    ];
                af[mt][1] = As[r + 8][ks + tg    ];
                af[mt][2] = As[r    ][ks + tg + 4];
                af[mt][3] = As[r + 8][ks + tg + 4];
            }
            #pragma unroll
            for (int nt = 0; nt < 4; nt++) {
                int r = wn * 32 + nt * 8 + g;
                bf[nt][0] = Bs[r][ks + tg    ];
                bf[nt][1] = Bs[r][ks + tg + 4];
            }
            #pragma unroll
            for (int mt = 0; mt < 4; mt++)
                #pragma unroll
                for (int nt = 0; nt < 4; nt++)
                    mma_tf32(c[mt][nt], af[mt][0], af[mt][1], af[mt][2], af[mt][3],
                             bf[nt][0], bf[nt][1]);
        }
    }

    #pragma unroll
    for (int mt = 0; mt < 4; mt++) {
        int row = blockIdx.y * 128 + wm * 64 + mt * 16 + g;
        #pragma unroll
        for (int nt = 0; nt < 4; nt++) {
            int col = blockIdx.x * 128 + wn * 32 + nt * 8 + 2 * tg;
            *(float2*)(C + (long)row * N + col)       = make_float2(c[mt][nt][0], c[mt][nt][1]);
            *(float2*)(C + (long)(row + 8) * N + col) = make_float2(c[mt][nt][2], c[mt][nt][3]);
        }
    }
}

// ---------------- fused RoPE + RMSNorm (one warp per (s,head) row) ----------
__global__ void rope_rmsnorm(float* __restrict__ t, const float* __restrict__ cosb,
                             const float* __restrict__ sinb, const float* __restrict__ w,
                             int nheads, int nrows)
{
    int row  = blockIdx.x * 8 + (threadIdx.x >> 5);
    if (row >= nrows) return;
    int lane = threadIdx.x & 31;
    int s    = row / nheads;

    float* p = t + row * HD;
    float2 xv = ((float2*)p)[lane];
    float c  = cosb[s * (HD / 2) + lane];
    float sn = sinb[s * (HD / 2) + lane];
    float orr = xv.x * c - xv.y * sn;
    float oi  = xv.x * sn + xv.y * c;

    float ss = orr * orr + oi * oi;
    #pragma unroll
    for (int o = 16; o; o >>= 1) ss += __shfl_xor_sync(0xffffffffu, ss, o);
    float inv = rsqrtf(ss * (1.f / HD) + 1e-6f);

    float2 wv = ((const float2*)w)[lane];
    ((float2*)p)[lane] = make_float2(orr * inv * wv.x, oi * inv * wv.y);
}

// ---------------- tensor-core flash attention (tf32) + fused sigmoid gate ---
// Block: 64 Q rows x 64 KV cols, 4 warps; warp w owns Q rows w*16..w*16+15.
// Ks[c][d] (tf32 bits, pad 68) reused as P[r][c] after the S phase.
// Vs[c][d]  (tf32 bits, pad 72) -> PV b-fragments conflict-free.
__global__ void __launch_bounds__(128) attn_tc(const float* __restrict__ q,
                                               const float* __restrict__ k,
                                               const float* __restrict__ v,
                                               const float* __restrict__ gate,
                                               float* __restrict__ o)
{
    __shared__ uint32_t Ks[64][68];
    __shared__ uint32_t Vs[64][72];
    uint32_t (*Ps)[68] = Ks;

    const int qb   = 31 - blockIdx.x;       // heavy blocks first
    const int h    = blockIdx.y;
    const int kvh  = h >> 2;                // NREP = 4
    const int tid  = threadIdx.x;
    const int lane = tid & 31;
    const int w    = tid >> 5;
    const int g    = lane >> 2;
    const int tg   = lane & 3;
    const int qi0  = qb * 64;

    // ---- stage Q (scaled by 1/sqrt(HD)) into Ks as raw floats ----
    {
        int r  = tid >> 1;
        int d0 = (tid & 1) * 32;
        const float* qp = q + ((qi0 + r) * NH + h) * HD + d0;
        #pragma unroll
        for (int u = 0; u < 8; u++) {
            float4 t4 = *(const float4*)(qp + u * 4);
            Ks[r][d0 + u*4 + 0] = __float_as_uint(t4.x * 0.125f);
            Ks[r][d0 + u*4 + 1] = __float_as_uint(t4.y * 0.125f);
            Ks[r][d0 + u*4 + 2] = __float_as_uint(t4.z * 0.125f);
            Ks[r][d0 + u*4 + 3] = __float_as_uint(t4.w * 0.125f);
        }
    }
    __syncthreads();

    // ---- pull Q fragments into registers (tf32) ----
    uint32_t qf[8][4];
    #pragma unroll
    for (int ks = 0; ks < 8; ks++) {
        qf[ks][0] = f2tf32(__uint_as_float(Ks[w*16 + g    ][ks*8 + tg    ]));
        qf[ks][1] = f2tf32(__uint_as_float(Ks[w*16 + g + 8][ks*8 + tg    ]));
        qf[ks][2] = f2tf32(__uint_as_float(Ks[w*16 + g    ][ks*8 + tg + 4]));
        qf[ks][3] = f2tf32(__uint_as_float(Ks[w*16 + g + 8][ks*8 + tg + 4]));
    }

    float oacc[8][4];
    #pragma unroll
    for (int nt = 0; nt < 8; nt++)
        #pragma unroll
        for (int r = 0; r < 4; r++) oacc[nt][r] = 0.f;
    float m0 = -1e30f, m1 = -1e30f, l0 = 0.f, l1 = 0.f;

    for (int kb = 0; kb <= qb; kb++) {
        __syncthreads();   // Q fragment reads (iter 0) / prev PV reads done

        // ---- load K, V tiles (convert to tf32 at store) ----
        {
            int c  = tid >> 1;
            int d0 = (tid & 1) * 32;
            const float* kp = k + ((kb*64 + c) * NKV + kvh) * HD + d0;
            const float* vp = v + ((kb*64 + c) * NKV + kvh) * HD + d0;
            #pragma unroll
            for (int u = 0; u < 8; u++) {
                float4 kt = *(const float4*)(kp + u * 4);
                float4 vt = *(const float4*)(vp + u * 4);
                Ks[c][d0 + u*4 + 0] = f2tf32(kt.x);
                Ks[c][d0 + u*4 + 1] = f2tf32(kt.y);
                Ks[c][d0 + u*4 + 2] = f2tf32(kt.z);
                Ks[c][d0 + u*4 + 3] = f2tf32(kt.w);
                Vs[c][d0 + u*4 + 0] = f2tf32(vt.x);
                Vs[c][d0 + u*4 + 1] = f2tf32(vt.y);
                Vs[c][d0 + u*4 + 2] = f2tf32(vt.z);
                Vs[c][d0 + u*4 + 3] = f2tf32(vt.w);
            }
        }
        __syncthreads();

        // ---- S = Q K^T  (warp: 16 rows x 64 cols) ----
        float sc[8][4];
        #pragma unroll
        for (int nt = 0; nt < 8; nt++)
            #pragma unroll
            for (int r = 0; r < 4; r++) sc[nt][r] = 0.f;

        #pragma unroll
        for (int ks = 0; ks < 8; ks++) {
            #pragma unroll
            for (int nt = 0; nt < 8; nt++) {
                uint32_t b0 = Ks[nt*8 + g][ks*8 + tg    ];
                uint32_t b1 = Ks[nt*8 + g][ks*8 + tg + 4];
                mma_tf32(sc[nt], qf[ks][0], qf[ks][1], qf[ks][2], qf[ks][3], b0, b1);
            }
        }

        // ---- causal mask on diagonal tile ----
        if (kb == qb) {
            int r0 = w*16 + g, r1 = r0 + 8;
            #pragma unroll
            for (int nt = 0; nt < 8; nt++) {
                int c0 = nt*8 + 2*tg, c1 = c0 + 1;
                if (c0 > r0) sc[nt][0] = -1e30f;
                if (c1 > r0) sc[nt][1] = -1e30f;
                if (c0 > r1) sc[nt][2] = -1e30f;
                if (c1 > r1) sc[nt][3] = -1e30f;
            }
        }

        // ---- online softmax (quad = one row) ----
        float mt0 = -1e30f, mt1 = -1e30f;
        #pragma unroll
        for (int nt = 0; nt < 8; nt++) {
            mt0 = fmaxf(mt0, fmaxf(sc[nt][0], sc[nt][1]));
            mt1 = fmaxf(mt1, fmaxf(sc[nt][2], sc[nt][3]));
        }
        mt0 = fmaxf(mt0, __shfl_xor_sync(0xffffffffu, mt0, 1));
        mt0 = fmaxf(mt0, __shfl_xor_sync(0xffffffffu, mt0, 2));
        mt1 = fmaxf(mt1, __shfl_xor_sync(0xffffffffu, mt1, 1));
        mt1 = fmaxf(mt1, __shfl_xor_sync(0xffffffffu, mt1, 2));

        float mn0 = fmaxf(m0, mt0), mn1 = fmaxf(m1, mt1);
        float a0 = __expf(m0 - mn0), a1 = __expf(m1 - mn1);
        m0 = mn0; m1 = mn1;

        float rs0 = 0.f, rs1 = 0.f;
        #pragma unroll
        for (int nt = 0; nt < 8; nt++) {
            sc[nt][0] = __expf(sc[nt][0] - mn0);
            sc[nt][1] = __expf(sc[nt][1] - mn0);
            sc[nt][2] = __expf(sc[nt][2] - mn1);
            sc[nt][3] = __expf(sc[nt][3] - mn1);
            rs0 += sc[nt][0] + sc[nt][1];
            rs1 += sc[nt][2] + sc[nt][3];
        }
        rs0 += __shfl_xor_sync(0xffffffffu, rs0, 1);
        rs0 += __shfl_xor_sync(0xffffffffu, rs0, 2);
        rs1 += __shfl_xor_sync(0xffffffffu, rs1, 1);
        rs1 += __shfl_xor_sync(0xffffffffu, rs1, 2);
        l0 = l0 * a0 + rs0;
        l1 = l1 * a1 + rs1;

        #pragma unroll
        for (int nt = 0; nt < 8; nt++) {
            oacc[nt][0] *= a0; oacc[nt][1] *= a0;
            oacc[nt][2] *= a1; oacc[nt][3] *= a1;
        }

        __syncthreads();   // all warps finished reading Ks -> safe to overwrite with P

        // ---- write P (tf32 bits) into Ps (= Ks) ----
        #pragma unroll
        for (int nt = 0; nt < 8; nt++) {
            int c0 = nt*8 + 2*tg;
            Ps[w*16 + g    ][c0    ] = f2tf32(sc[nt][0]);
            Ps[w*16 + g    ][c0 + 1] = f2tf32(sc[nt][1]);
            Ps[w*16 + g + 8][c0    ] = f2tf32(sc[nt][2]);
            Ps[w*16 + g + 8][c0 + 1] = f2tf32(sc[nt][3]);
        }
        __syncthreads();

        // ---- O += P V ----
        #pragma unroll
        for (int ks = 0; ks < 8; ks++) {
            uint32_t p0 = Ps[w*16 + g    ][ks*8 + tg    ];
            uint32_t p1 = Ps[w*16 + g + 8][ks*8 + tg    ];
            uint32_t p2 = Ps[w*16 + g    ][ks*8 + tg + 4];
            uint32_t p3 = Ps[w*16 + g + 8][ks*8 + tg + 4];
            #pragma unroll
            for (int nt = 0; nt < 8; nt++) {
                uint32_t b0 = Vs[ks*8 + tg    ][nt*8 + g];
                uint32_t b1 = Vs[ks*8 + tg + 4][nt*8 + g];
                mma_tf32(oacc[nt], p0, p1, p2, p3, b0, b1);
            }
        }
    }

    // ---- epilogue: normalize + fused sigmoid gate ----
    float invl0 = 1.f / l0, invl1 = 1.f / l1;
    int row0 = qi0 + w*16 + g;
    int row1 = row0 + 8;
    #pragma unroll
    for (int nt = 0; nt < 8; nt++) {
        int d = nt*8 + 2*tg;
        const float* gp0 = gate + row0 * DIM + h * HD + d;
        const float* gp1 = gate + row1 * DIM + h * HD + d;
        float2 ga = *(const float2*)gp0;
        float2 gb = *(const float2*)gp1;
        float2 o0, o1;
        o0.x = oacc[nt][0] * invl0 * (1.f / (1.f + __expf(-ga.x)));
        o0.y = oacc[nt][1] * invl0 * (1.f / (1.f + __expf(-ga.y)));
        o1.x = oacc[nt][2] * invl1 * (1.f / (1.f + __expf(-gb.x)));
        o1.y = oacc[nt][3] * invl1 * (1.f / (1.f + __expf(-gb.y)));
        *(float2*)(o + row0 * DIM + h * HD + d) = o0;
        *(float2*)(o + row1 * DIM + h * HD + d) = o1;
    }
}

// ---------------- launcher ---------------------------------------------------
extern "C" void kernel_launch(void* const* d_in, const int* in_sizes, int n_in,
                              void* d_out, int out_size)
{
    const float* x    = (const float*)d_in[0];
    const float* cosb = (const float*)d_in[1];
    const float* sinb = (const float*)d_in[2];
    const float* wq   = (const float*)d_in[3];
    const float* wk   = (const float*)d_in[4];
    const float* wv   = (const float*)d_in[5];
    const float* wo   = (const float*)d_in[6];
    const float* wg   = (const float*)d_in[7];
    const float* qn   = (const float*)d_in[8];
    const float* kn   = (const float*)d_in[9];
    float* out = (float*)d_out;

    float *qb, *kb, *vb, *gb, *ab;
    cudaGetSymbolAddress((void**)&qb, g_q);
    cudaGetSymbolAddress((void**)&kb, g_k);
    cudaGetSymbolAddress((void**)&vb, g_v);
    cudaGetSymbolAddress((void**)&gb, g_gate);
    cudaGetSymbolAddress((void**)&ab, g_att);

    // projections (tensor cores, tf32)
    gemm_tf32<<<dim3(DIM / 128, SEQ / 128), 256>>>(x, wq, qb, SEQ, DIM, DIM);
    gemm_tf32<<<dim3((NKV * HD) / 128, SEQ / 128), 256>>>(x, wk, kb, SEQ, NKV * HD, DIM);
    gemm_tf32<<<dim3((NKV * HD) / 128, SEQ / 128), 256>>>(x, wv, vb, SEQ, NKV * HD, DIM);
    gemm_tf32<<<dim3(DIM / 128, SEQ / 128), 256>>>(x, wg, gb, SEQ, DIM, DIM);

    // RoPE + RMSNorm
    rope_rmsnorm<<<(SEQ * NH) / 8, 256>>>(qb, cosb, sinb, qn, NH, SEQ * NH);
    rope_rmsnorm<<<(SEQ * NKV) / 8, 256>>>(kb, cosb, sinb, kn, NKV, SEQ * NKV);

    // tensor-core causal GQA flash attention + fused sigmoid gate
    attn_tc<<<dim3(SEQ / 64, NH), 128>>>(qb, kb, vb, gb, ab);

    // output projection (tensor cores, tf32)
    gemm_tf32<<<dim3(DIM / 128, SEQ / 128), 256>>>(ab, wo, out, SEQ, DIM, DIM);
}

// round 7
// speedup vs baseline: 4.6329x; 1.1822x over previous
#include <cuda_runtime.h>
#include <cuda_bf16.h>
#include <cstdint>

#define SEQ 2048
#define DIM 2048
#define NH 32
#define NKV 8
#define HD 64

// ---------------- scratch (static device globals; no runtime alloc) ----------
__device__ float g_q[SEQ * NH * HD];
__device__ float g_k[SEQ * NKV * HD];
__device__ float g_v[SEQ * NKV * HD];
__device__ float g_gate[SEQ * DIM];
__device__ float g_att[SEQ * DIM];

// ---------------- helpers ----------------------------------------------------
__device__ __forceinline__ uint32_t f2tf32(float f) {
    uint32_t r;
    asm("cvt.rna.tf32.f32 %0, %1;" : "=r"(r) : "f"(f));
    return r;
}

__device__ __forceinline__ float ex2(float x) {
    float y;
    asm("ex2.approx.ftz.f32 %0, %1;" : "=f"(y) : "f"(x));
    return y;
}

__device__ __forceinline__ void mma_tf32(float c[4],
                                         uint32_t a0, uint32_t a1, uint32_t a2, uint32_t a3,
                                         uint32_t b0, uint32_t b1)
{
    asm volatile(
        "mma.sync.aligned.m16n8k8.row.col.f32.tf32.tf32.f32 "
        "{%0,%1,%2,%3}, {%4,%5,%6,%7}, {%8,%9}, {%0,%1,%2,%3};"
        : "+f"(c[0]), "+f"(c[1]), "+f"(c[2]), "+f"(c[3])
        : "r"(a0), "r"(a1), "r"(a2), "r"(a3), "r"(b0), "r"(b1));
}

#define LDSM4(r0, r1, r2, r3, addr) \
    asm volatile("ldmatrix.sync.aligned.m8n8.x4.shared.b16 {%0,%1,%2,%3}, [%4];" \
        : "=r"(r0), "=r"(r1), "=r"(r2), "=r"(r3) : "r"(addr))

__device__ __forceinline__ uint32_t smem_u32(const void* p) {
    return (uint32_t)__cvta_generic_to_shared(p);
}

// ---------------- tensor-core GEMM: C[M][N] = A[M][K] * B[N][K]^T -----------
// BM=BN=128, BK=16, 8 warps (2x4), warp tile 64x32, double-buffered smem,
// ldmatrix fragments. Stride-20 padding: every LDSM phase conflict-free.
__global__ void __launch_bounds__(256, 2) gemm_tf32(const float* __restrict__ A,
                                                    const float* __restrict__ B,
                                                    float* __restrict__ C,
                                                    int M, int N, int K)
{
    __shared__ uint32_t As[2][128][20];
    __shared__ uint32_t Bs[2][128][20];
    const uint32_t STAGE = 128 * 20 * 4;   // bytes per stage

    const int tid  = threadIdx.x;
    const int lane = tid & 31;
    const int warp = tid >> 5;
    const int wm   = warp & 1;
    const int wn   = warp >> 1;
    const int g    = lane >> 2;
    const int tg   = lane & 3;

    const int lrow = tid >> 1;
    const int lcol = (tid & 1) * 8;

    const float* Ag = A + (blockIdx.y * 128 + lrow) * (long)K + lcol;
    const float* Bg = B + (blockIdx.x * 128 + lrow) * (long)K + lcol;

    // ldmatrix per-thread base addresses (stage 0)
    const uint32_t a_base = smem_u32(&As[0][wm * 64 + (lane & 15)][(lane & 16) ? 4 : 0]);
    const uint32_t b_base = smem_u32(&Bs[0][wn * 32 + (lane & 7) + ((lane & 16) >> 1)][(lane & 8) ? 4 : 0]);

    float c[4][4][4];
    #pragma unroll
    for (int mt = 0; mt < 4; mt++)
        #pragma unroll
        for (int nt = 0; nt < 4; nt++)
            #pragma unroll
            for (int r = 0; r < 4; r++) c[mt][nt][r] = 0.f;

    // prologue: tile 0 -> stage 0, prefetch tile 1 into regs
    float4 pa0 = *(const float4*)(Ag + 0);
    float4 pa1 = *(const float4*)(Ag + 4);
    float4 pb0 = *(const float4*)(Bg + 0);
    float4 pb1 = *(const float4*)(Bg + 4);
    As[0][lrow][lcol + 0] = f2tf32(pa0.x); As[0][lrow][lcol + 1] = f2tf32(pa0.y);
    As[0][lrow][lcol + 2] = f2tf32(pa0.z); As[0][lrow][lcol + 3] = f2tf32(pa0.w);
    As[0][lrow][lcol + 4] = f2tf32(pa1.x); As[0][lrow][lcol + 5] = f2tf32(pa1.y);
    As[0][lrow][lcol + 6] = f2tf32(pa1.z); As[0][lrow][lcol + 7] = f2tf32(pa1.w);
    Bs[0][lrow][lcol + 0] = f2tf32(pb0.x); Bs[0][lrow][lcol + 1] = f2tf32(pb0.y);
    Bs[0][lrow][lcol + 2] = f2tf32(pb0.z); Bs[0][lrow][lcol + 3] = f2tf32(pb0.w);
    Bs[0][lrow][lcol + 4] = f2tf32(pb1.x); Bs[0][lrow][lcol + 5] = f2tf32(pb1.y);
    Bs[0][lrow][lcol + 6] = f2tf32(pb1.z); Bs[0][lrow][lcol + 7] = f2tf32(pb1.w);
    pa0 = *(const float4*)(Ag + 16); pa1 = *(const float4*)(Ag + 20);
    pb0 = *(const float4*)(Bg + 16); pb1 = *(const float4*)(Bg + 20);
    __syncthreads();

    for (int kb = 0; kb < K; kb += 16) {
        const int st = (kb >> 4) & 1;

        // store tile kb+16 (regs from prev iter's LDG) into the other stage
        if (kb + 16 < K) {
            const int so = st ^ 1;
            As[so][lrow][lcol + 0] = f2tf32(pa0.x); As[so][lrow][lcol + 1] = f2tf32(pa0.y);
            As[so][lrow][lcol + 2] = f2tf32(pa0.z); As[so][lrow][lcol + 3] = f2tf32(pa0.w);
            As[so][lrow][lcol + 4] = f2tf32(pa1.x); As[so][lrow][lcol + 5] = f2tf32(pa1.y);
            As[so][lrow][lcol + 6] = f2tf32(pa1.z); As[so][lrow][lcol + 7] = f2tf32(pa1.w);
            Bs[so][lrow][lcol + 0] = f2tf32(pb0.x); Bs[so][lrow][lcol + 1] = f2tf32(pb0.y);
            Bs[so][lrow][lcol + 2] = f2tf32(pb0.z); Bs[so][lrow][lcol + 3] = f2tf32(pb0.w);
            Bs[so][lrow][lcol + 4] = f2tf32(pb1.x); Bs[so][lrow][lcol + 5] = f2tf32(pb1.y);
            Bs[so][lrow][lcol + 6] = f2tf32(pb1.z); Bs[so][lrow][lcol + 7] = f2tf32(pb1.w);
        }
        // issue LDG for tile kb+32 (completes during this iter's compute)
        if (kb + 32 < K) {
            pa0 = *(const float4*)(Ag + kb + 32); pa1 = *(const float4*)(Ag + kb + 36);
            pb0 = *(const float4*)(Bg + kb + 32); pb1 = *(const float4*)(Bg + kb + 36);
        }

        const uint32_t aa = a_base + st * STAGE;
        const uint32_t bb = b_base + st * STAGE;
        #pragma unroll
        for (int ks = 0; ks < 16; ks += 8) {
            uint32_t af[4][4];
            uint32_t bf[4][2];
            #pragma unroll
            for (int mt = 0; mt < 4; mt++)
                LDSM4(af[mt][0], af[mt][1], af[mt][2], af[mt][3],
                      aa + (mt * 16 * 20 + ks) * 4);
            #pragma unroll
            for (int np = 0; np < 2; np++)
                LDSM4(bf[2*np][0], bf[2*np][1], bf[2*np+1][0], bf[2*np+1][1],
                      bb + (np * 16 * 20 + ks) * 4);
            #pragma unroll
            for (int mt = 0; mt < 4; mt++)
                #pragma unroll
                for (int nt = 0; nt < 4; nt++)
                    mma_tf32(c[mt][nt], af[mt][0], af[mt][1], af[mt][2], af[mt][3],
                             bf[nt][0], bf[nt][1]);
        }
        __syncthreads();
    }

    #pragma unroll
    for (int mt = 0; mt < 4; mt++) {
        int row = blockIdx.y * 128 + wm * 64 + mt * 16 + g;
        #pragma unroll
        for (int nt = 0; nt < 4; nt++) {
            int col = blockIdx.x * 128 + wn * 32 + nt * 8 + 2 * tg;
            *(float2*)(C + (long)row * N + col)       = make_float2(c[mt][nt][0], c[mt][nt][1]);
            *(float2*)(C + (long)(row + 8) * N + col) = make_float2(c[mt][nt][2], c[mt][nt][3]);
        }
    }
}

// ---------------- fused RoPE + RMSNorm (one warp per (s,head) row) ----------
__global__ void rope_rmsnorm(float* __restrict__ t, const float* __restrict__ cosb,
                             const float* __restrict__ sinb, const float* __restrict__ w,
                             int nheads, int nrows)
{
    int row  = blockIdx.x * 8 + (threadIdx.x >> 5);
    if (row >= nrows) return;
    int lane = threadIdx.x & 31;
    int s    = row / nheads;

    float* p = t + row * HD;
    float2 xv = ((float2*)p)[lane];
    float c  = cosb[s * (HD / 2) + lane];
    float sn = sinb[s * (HD / 2) + lane];
    float orr = xv.x * c - xv.y * sn;
    float oi  = xv.x * sn + xv.y * c;

    float ss = orr * orr + oi * oi;
    #pragma unroll
    for (int o = 16; o; o >>= 1) ss += __shfl_xor_sync(0xffffffffu, ss, o);
    float inv = rsqrtf(ss * (1.f / HD) + 1e-6f);

    float2 wv = ((const float2*)w)[lane];
    ((float2*)p)[lane] = make_float2(orr * inv * wv.x, oi * inv * wv.y);
}

// ---------------- tensor-core flash attention (tf32) + fused sigmoid gate ---
// 64 Q rows x 64 KV cols, 4 warps. Softmax in exp2 domain (log2e folded into
// Q scale). Q and K fragments via ldmatrix; P stays in registers and is
// reshuffled into PV A-fragments with shfl (no smem round-trip).
__global__ void __launch_bounds__(128) attn_tc(const float* __restrict__ q,
                                               const float* __restrict__ k,
                                               const float* __restrict__ v,
                                               const float* __restrict__ gate,
                                               float* __restrict__ o)
{
    __shared__ uint32_t Ks[64][68];
    __shared__ uint32_t Vs[64][72];

    const float SCALE = 0.125f * 1.44269504088896f;   // 1/sqrt(64) * log2(e)

    const int qb   = 31 - blockIdx.x;       // heavy blocks first
    const int h    = blockIdx.y;
    const int kvh  = h >> 2;                // NREP = 4
    const int tid  = threadIdx.x;
    const int lane = tid & 31;
    const int w    = tid >> 5;
    const int g    = lane >> 2;
    const int tg   = lane & 3;
    const int qi0  = qb * 64;

    // ---- stage Q (scaled, tf32) into Ks ----
    {
        int r  = tid >> 1;
        int d0 = (tid & 1) * 32;
        const float* qp = q + ((qi0 + r) * NH + h) * HD + d0;
        #pragma unroll
        for (int u = 0; u < 8; u++) {
            float4 t4 = *(const float4*)(qp + u * 4);
            Ks[r][d0 + u*4 + 0] = f2tf32(t4.x * SCALE);
            Ks[r][d0 + u*4 + 1] = f2tf32(t4.y * SCALE);
            Ks[r][d0 + u*4 + 2] = f2tf32(t4.z * SCALE);
            Ks[r][d0 + u*4 + 3] = f2tf32(t4.w * SCALE);
        }
    }
    __syncthreads();

    // ---- Q fragments via ldmatrix ----
    uint32_t qf[8][4];
    {
        const uint32_t qaddr = smem_u32(&Ks[w * 16 + (lane & 15)][(lane & 16) ? 4 : 0]);
        #pragma unroll
        for (int ks = 0; ks < 8; ks++)
            LDSM4(qf[ks][0], qf[ks][1], qf[ks][2], qf[ks][3], qaddr + ks * 32);
    }

    const uint32_t kaddr = smem_u32(&Ks[(lane & 7) + ((lane & 16) >> 1)][(lane & 8) ? 4 : 0]);

    float oacc[8][4];
    #pragma unroll
    for (int nt = 0; nt < 8; nt++)
        #pragma unroll
        for (int r = 0; r < 4; r++) oacc[nt][r] = 0.f;
    float m0 = -1e30f, m1 = -1e30f, l0 = 0.f, l1 = 0.f;

    const int sbase = lane & ~3;
    const int s0l   = sbase + (tg >> 1);
    const int s2l   = s0l + 2;
    const bool odd  = tg & 1;

    for (int kb = 0; kb <= qb; kb++) {
        __syncthreads();   // prior tile's Ks/Vs reads done (and qf reads on iter 0)

        // ---- load K, V tiles (tf32 at store) ----
        {
            int c  = tid >> 1;
            int d0 = (tid & 1) * 32;
            const float* kp = k + ((kb*64 + c) * NKV + kvh) * HD + d0;
            const float* vp = v + ((kb*64 + c) * NKV + kvh) * HD + d0;
            #pragma unroll
            for (int u = 0; u < 8; u++) {
                float4 kt = *(const float4*)(kp + u * 4);
                float4 vt = *(const float4*)(vp + u * 4);
                Ks[c][d0 + u*4 + 0] = f2tf32(kt.x);
                Ks[c][d0 + u*4 + 1] = f2tf32(kt.y);
                Ks[c][d0 + u*4 + 2] = f2tf32(kt.z);
                Ks[c][d0 + u*4 + 3] = f2tf32(kt.w);
                Vs[c][d0 + u*4 + 0] = f2tf32(vt.x);
                Vs[c][d0 + u*4 + 1] = f2tf32(vt.y);
                Vs[c][d0 + u*4 + 2] = f2tf32(vt.z);
                Vs[c][d0 + u*4 + 3] = f2tf32(vt.w);
            }
        }
        __syncthreads();

        // ---- S = Q K^T (K fragments via ldmatrix) ----
        float sc[8][4];
        #pragma unroll
        for (int nt = 0; nt < 8; nt++)
            #pragma unroll
            for (int r = 0; r < 4; r++) sc[nt][r] = 0.f;

        #pragma unroll
        for (int ks = 0; ks < 8; ks++) {
            #pragma unroll
            for (int np = 0; np < 4; np++) {
                uint32_t b00, b01, b10, b11;
                LDSM4(b00, b01, b10, b11, kaddr + (np * 16 * 68 + ks * 8) * 4);
                mma_tf32(sc[2*np],   qf[ks][0], qf[ks][1], qf[ks][2], qf[ks][3], b00, b01);
                mma_tf32(sc[2*np+1], qf[ks][0], qf[ks][1], qf[ks][2], qf[ks][3], b10, b11);
            }
        }

        // ---- causal mask on diagonal tile ----
        if (kb == qb) {
            int r0 = w*16 + g, r1 = r0 + 8;
            #pragma unroll
            for (int nt = 0; nt < 8; nt++) {
                int c0 = nt*8 + 2*tg, c1 = c0 + 1;
                if (c0 > r0) sc[nt][0] = -1e30f;
                if (c1 > r0) sc[nt][1] = -1e30f;
                if (c0 > r1) sc[nt][2] = -1e30f;
                if (c1 > r1) sc[nt][3] = -1e30f;
            }
        }

        // ---- online softmax (exp2 domain; quad = one row) ----
        float mt0 = -1e30f, mt1 = -1e30f;
        #pragma unroll
        for (int nt = 0; nt < 8; nt++) {
            mt0 = fmaxf(mt0, fmaxf(sc[nt][0], sc[nt][1]));
            mt1 = fmaxf(mt1, fmaxf(sc[nt][2], sc[nt][3]));
        }
        mt0 = fmaxf(mt0, __shfl_xor_sync(0xffffffffu, mt0, 1));
        mt0 = fmaxf(mt0, __shfl_xor_sync(0xffffffffu, mt0, 2));
        mt1 = fmaxf(mt1, __shfl_xor_sync(0xffffffffu, mt1, 1));
        mt1 = fmaxf(mt1, __shfl_xor_sync(0xffffffffu, mt1, 2));

        float mn0 = fmaxf(m0, mt0), mn1 = fmaxf(m1, mt1);
        float a0 = ex2(m0 - mn0), a1 = ex2(m1 - mn1);
        m0 = mn0; m1 = mn1;

        float rs0 = 0.f, rs1 = 0.f;
        uint32_t pr[8][4];
        #pragma unroll
        for (int nt = 0; nt < 8; nt++) {
            sc[nt][0] = ex2(sc[nt][0] - mn0);
            sc[nt][1] = ex2(sc[nt][1] - mn0);
            sc[nt][2] = ex2(sc[nt][2] - mn1);
            sc[nt][3] = ex2(sc[nt][3] - mn1);
            rs0 += sc[nt][0] + sc[nt][1];
            rs1 += sc[nt][2] + sc[nt][3];
            pr[nt][0] = f2tf32(sc[nt][0]);
            pr[nt][1] = f2tf32(sc[nt][1]);
            pr[nt][2] = f2tf32(sc[nt][2]);
            pr[nt][3] = f2tf32(sc[nt][3]);
        }
        rs0 += __shfl_xor_sync(0xffffffffu, rs0, 1);
        rs0 += __shfl_xor_sync(0xffffffffu, rs0, 2);
        rs1 += __shfl_xor_sync(0xffffffffu, rs1, 1);
        rs1 += __shfl_xor_sync(0xffffffffu, rs1, 2);
        l0 = l0 * a0 + rs0;
        l1 = l1 * a1 + rs1;

        #pragma unroll
        for (int nt = 0; nt < 8; nt++) {
            oacc[nt][0] *= a0; oacc[nt][1] *= a0;
            oacc[nt][2] *= a1; oacc[nt][3] *= a1;
        }

        // ---- O += P V : reshuffle P accumulators into A-fragments (shfl) ----
        #pragma unroll
        for (int ks = 0; ks < 8; ks++) {
            uint32_t u00 = __shfl_sync(0xffffffffu, pr[ks][0], s0l);
            uint32_t u01 = __shfl_sync(0xffffffffu, pr[ks][1], s0l);
            uint32_t u20 = __shfl_sync(0xffffffffu, pr[ks][2], s0l);
            uint32_t u21 = __shfl_sync(0xffffffffu, pr[ks][3], s0l);
            uint32_t v00 = __shfl_sync(0xffffffffu, pr[ks][0], s2l);
            uint32_t v01 = __shfl_sync(0xffffffffu, pr[ks][1], s2l);
            uint32_t v20 = __shfl_sync(0xffffffffu, pr[ks][2], s2l);
            uint32_t v21 = __shfl_sync(0xffffffffu, pr[ks][3], s2l);
            uint32_t pa0 = odd ? u01 : u00;   // P[g   ][8ks+tg  ]
            uint32_t pa1 = odd ? u21 : u20;   // P[g+8 ][8ks+tg  ]
            uint32_t pa2 = odd ? v01 : v00;   // P[g   ][8ks+tg+4]
            uint32_t pa3 = odd ? v21 : v20;   // P[g+8 ][8ks+tg+4]
            #pragma unroll
            for (int nt = 0; nt < 8; nt++) {
                uint32_t b0 = Vs[ks*8 + tg    ][nt*8 + g];
                uint32_t b1 = Vs[ks*8 + tg + 4][nt*8 + g];
                mma_tf32(oacc[nt], pa0, pa1, pa2, pa3, b0, b1);
            }
        }
    }

    // ---- epilogue: normalize + fused sigmoid gate ----
    float invl0 = 1.f / l0, invl1 = 1.f / l1;
    int row0 = qi0 + w*16 + g;
    int row1 = row0 + 8;
    #pragma unroll
    for (int nt = 0; nt < 8; nt++) {
        int d = nt*8 + 2*tg;
        float2 ga = *(const float2*)(gate + row0 * DIM + h * HD + d);
        float2 gb = *(const float2*)(gate + row1 * DIM + h * HD + d);
        float2 o0, o1;
        o0.x = oacc[nt][0] * invl0 * (1.f / (1.f + __expf(-ga.x)));
        o0.y = oacc[nt][1] * invl0 * (1.f / (1.f + __expf(-ga.y)));
        o1.x = oacc[nt][2] * invl1 * (1.f / (1.f + __expf(-gb.x)));
        o1.y = oacc[nt][3] * invl1 * (1.f / (1.f + __expf(-gb.y)));
        *(float2*)(o + row0 * DIM + h * HD + d) = o0;
        *(float2*)(o + row1 * DIM + h * HD + d) = o1;
    }
}

// ---------------- launcher ---------------------------------------------------
extern "C" void kernel_launch(void* const* d_in, const int* in_sizes, int n_in,
                              void* d_out, int out_size)
{
    const float* x    = (const float*)d_in[0];
    const float* cosb = (const float*)d_in[1];
    const float* sinb = (const float*)d_in[2];
    const float* wq   = (const float*)d_in[3];
    const float* wk   = (const float*)d_in[4];
    const float* wv   = (const float*)d_in[5];
    const float* wo   = (const float*)d_in[6];
    const float* wg   = (const float*)d_in[7];
    const float* qn   = (const float*)d_in[8];
    const float* kn   = (const float*)d_in[9];
    float* out = (float*)d_out;

    float *qb, *kb, *vb, *gb, *ab;
    cudaGetSymbolAddress((void**)&qb, g_q);
    cudaGetSymbolAddress((void**)&kb, g_k);
    cudaGetSymbolAddress((void**)&vb, g_v);
    cudaGetSymbolAddress((void**)&gb, g_gate);
    cudaGetSymbolAddress((void**)&ab, g_att);

    gemm_tf32<<<dim3(DIM / 128, SEQ / 128), 256>>>(x, wq, qb, SEQ, DIM, DIM);
    gemm_tf32<<<dim3((NKV * HD) / 128, SEQ / 128), 256>>>(x, wk, kb, SEQ, NKV * HD, DIM);
    gemm_tf32<<<dim3((NKV * HD) / 128, SEQ / 128), 256>>>(x, wv, vb, SEQ, NKV * HD, DIM);
    gemm_tf32<<<dim3(DIM / 128, SEQ / 128), 256>>>(x, wg, gb, SEQ, DIM, DIM);

    rope_rmsnorm<<<(SEQ * NH) / 8, 256>>>(qb, cosb, sinb, qn, NH, SEQ * NH);
    rope_rmsnorm<<<(SEQ * NKV) / 8, 256>>>(kb, cosb, sinb, kn, NKV, SEQ * NKV);

    attn_tc<<<dim3(SEQ / 64, NH), 128>>>(qb, kb, vb, gb, ab);

    gemm_tf32<<<dim3(DIM / 128, SEQ / 128), 256>>>(ab, wo, out, SEQ, DIM, DIM);
}

// round 8
// speedup vs baseline: 5.5854x; 1.2056x over previous
#include <cuda_runtime.h>
#include <cuda_bf16.h>
#include <cstdint>

#define SEQ 2048
#define DIM 2048
#define NH 32
#define NKV 8
#define HD 64

// ---------------- scratch (static device globals; no runtime alloc) ----------
__device__ float g_q[SEQ * NH * HD];
__device__ float g_k[SEQ * NKV * HD];
__device__ float g_v[SEQ * NKV * HD];
__device__ float g_gate[SEQ * DIM];
__device__ float g_att[SEQ * DIM];

// ---------------- helpers ----------------------------------------------------
__device__ __forceinline__ uint32_t f2tf32(float f) {
    uint32_t r;
    asm("cvt.rna.tf32.f32 %0, %1;" : "=r"(r) : "f"(f));
    return r;
}

__device__ __forceinline__ float ex2(float x) {
    float y;
    asm("ex2.approx.ftz.f32 %0, %1;" : "=f"(y) : "f"(x));
    return y;
}

__device__ __forceinline__ void mma_tf32(float c[4],
                                         uint32_t a0, uint32_t a1, uint32_t a2, uint32_t a3,
                                         uint32_t b0, uint32_t b1)
{
    asm volatile(
        "mma.sync.aligned.m16n8k8.row.col.f32.tf32.tf32.f32 "
        "{%0,%1,%2,%3}, {%4,%5,%6,%7}, {%8,%9}, {%0,%1,%2,%3};"
        : "+f"(c[0]), "+f"(c[1]), "+f"(c[2]), "+f"(c[3])
        : "r"(a0), "r"(a1), "r"(a2), "r"(a3), "r"(b0), "r"(b1));
}

#define LDSM4(r0, r1, r2, r3, addr) \
    asm volatile("ldmatrix.sync.aligned.m8n8.x4.shared.b16 {%0,%1,%2,%3}, [%4];" \
        : "=r"(r0), "=r"(r1), "=r"(r2), "=r"(r3) : "r"(addr))

#define CP16(dst, src) \
    asm volatile("cp.async.cg.shared.global [%0], [%1], 16;" :: "r"(dst), "l"(src))
#define CP_COMMIT() asm volatile("cp.async.commit_group;")
#define CP_WAIT(n)  asm volatile("cp.async.wait_group %0;" :: "n"(n))

__device__ __forceinline__ uint32_t smem_u32(const void* p) {
    return (uint32_t)__cvta_generic_to_shared(p);
}

// ---------------- big GEMM: 4 warps, warp tile 64x64, 1 sync/iter -----------
// C[M][N] = A[M][K] * B[N][K]^T, BM=BN=128, BK=16, 128 threads (2x2 warps).
__global__ void __launch_bounds__(128, 2) gemm_big(const float* __restrict__ A,
                                                   const float* __restrict__ B,
                                                   float* __restrict__ C,
                                                   int M, int N, int K)
{
    __shared__ uint32_t As[2][128][20];
    __shared__ uint32_t Bs[2][128][20];
    const uint32_t STAGE = 128 * 20 * 4;

    const int tid  = threadIdx.x;
    const int lane = tid & 31;
    const int warp = tid >> 5;           // 0..3
    const int wm   = warp & 1;           // 64-row half
    const int wn   = warp >> 1;          // 64-col half
    const int g    = lane >> 2;
    const int tg   = lane & 3;

    const int ar = tid >> 2;             // 0..31 (rows ar, ar+32, ar+64, ar+96)
    const int ac = (tid & 3) * 4;        // 0,4,8,12

    const float* Ag = A + (blockIdx.y * 128 + ar) * (long)K + ac;
    const float* Bg = B + (blockIdx.x * 128 + ar) * (long)K + ac;

    const uint32_t a_base = smem_u32(&As[0][wm * 64 + (lane & 15)][(lane & 16) ? 4 : 0]);
    const uint32_t b_base = smem_u32(&Bs[0][wn * 64 + (lane & 7) + ((lane & 16) >> 1)][(lane & 8) ? 4 : 0]);

    float c[4][8][4];
    #pragma unroll
    for (int mt = 0; mt < 4; mt++)
        #pragma unroll
        for (int nt = 0; nt < 8; nt++)
            #pragma unroll
            for (int r = 0; r < 4; r++) c[mt][nt][r] = 0.f;

    float4 la[4], lb[4];
    // prologue: LDG tile 0, store to stage 0
    #pragma unroll
    for (int u = 0; u < 4; u++) {
        la[u] = *(const float4*)(Ag + (long)u * 32 * K);
        lb[u] = *(const float4*)(Bg + (long)u * 32 * K);
    }
    #pragma unroll
    for (int u = 0; u < 4; u++) {
        *(uint4*)&As[0][u * 32 + ar][ac] =
            make_uint4(f2tf32(la[u].x), f2tf32(la[u].y), f2tf32(la[u].z), f2tf32(la[u].w));
        *(uint4*)&Bs[0][u * 32 + ar][ac] =
            make_uint4(f2tf32(lb[u].x), f2tf32(lb[u].y), f2tf32(lb[u].z), f2tf32(lb[u].w));
    }

    const int T = K >> 4;
    for (int t = 0; t < T; t++) {
        const int st = t & 1;
        if (t + 1 < T) {                  // LDG next tile (overlaps compute)
            #pragma unroll
            for (int u = 0; u < 4; u++) {
                la[u] = *(const float4*)(Ag + (t + 1) * 16 + (long)u * 32 * K);
                lb[u] = *(const float4*)(Bg + (t + 1) * 16 + (long)u * 32 * K);
            }
        }
        __syncthreads();                  // stage st stores (prev iter) visible

        const uint32_t aa = a_base + st * STAGE;
        const uint32_t bb = b_base + st * STAGE;
        #pragma unroll
        for (int ks = 0; ks < 16; ks += 8) {
            uint32_t af[4][4], bf[8][2];
            #pragma unroll
            for (int mt = 0; mt < 4; mt++)
                LDSM4(af[mt][0], af[mt][1], af[mt][2], af[mt][3],
                      aa + (mt * 16 * 20 + ks) * 4);
            #pragma unroll
            for (int np = 0; np < 4; np++)
                LDSM4(bf[2*np][0], bf[2*np][1], bf[2*np+1][0], bf[2*np+1][1],
                      bb + (np * 16 * 20 + ks) * 4);
            #pragma unroll
            for (int mt = 0; mt < 4; mt++)
                #pragma unroll
                for (int nt = 0; nt < 8; nt++)
                    mma_tf32(c[mt][nt], af[mt][0], af[mt][1], af[mt][2], af[mt][3],
                             bf[nt][0], bf[nt][1]);
        }

        if (t + 1 < T) {                  // store next tile into other stage
            const int so = st ^ 1;
            #pragma unroll
            for (int u = 0; u < 4; u++) {
                *(uint4*)&As[so][u * 32 + ar][ac] =
                    make_uint4(f2tf32(la[u].x), f2tf32(la[u].y), f2tf32(la[u].z), f2tf32(la[u].w));
                *(uint4*)&Bs[so][u * 32 + ar][ac] =
                    make_uint4(f2tf32(lb[u].x), f2tf32(lb[u].y), f2tf32(lb[u].z), f2tf32(lb[u].w));
            }
        }
    }

    #pragma unroll
    for (int mt = 0; mt < 4; mt++) {
        int row = blockIdx.y * 128 + wm * 64 + mt * 16 + g;
        #pragma unroll
        for (int nt = 0; nt < 8; nt++) {
            int col = blockIdx.x * 128 + wn * 64 + nt * 8 + 2 * tg;
            *(float2*)(C + (long)row * N + col)       = make_float2(c[mt][nt][0], c[mt][nt][1]);
            *(float2*)(C + (long)(row + 8) * N + col) = make_float2(c[mt][nt][2], c[mt][nt][3]);
        }
    }
}

// ---------------- 8-warp GEMM (kept for the narrow K/V projections) ---------
__global__ void __launch_bounds__(256, 2) gemm_tf32(const float* __restrict__ A,
                                                    const float* __restrict__ B,
                                                    float* __restrict__ C,
                                                    int M, int N, int K)
{
    __shared__ uint32_t As[2][128][20];
    __shared__ uint32_t Bs[2][128][20];
    const uint32_t STAGE = 128 * 20 * 4;

    const int tid  = threadIdx.x;
    const int lane = tid & 31;
    const int warp = tid >> 5;
    const int wm   = warp & 1;
    const int wn   = warp >> 1;
    const int g    = lane >> 2;
    const int tg   = lane & 3;

    const int lrow = tid >> 1;
    const int lcol = (tid & 1) * 8;

    const float* Ag = A + (blockIdx.y * 128 + lrow) * (long)K + lcol;
    const float* Bg = B + (blockIdx.x * 128 + lrow) * (long)K + lcol;

    const uint32_t a_base = smem_u32(&As[0][wm * 64 + (lane & 15)][(lane & 16) ? 4 : 0]);
    const uint32_t b_base = smem_u32(&Bs[0][wn * 32 + (lane & 7) + ((lane & 16) >> 1)][(lane & 8) ? 4 : 0]);

    float c[4][4][4];
    #pragma unroll
    for (int mt = 0; mt < 4; mt++)
        #pragma unroll
        for (int nt = 0; nt < 4; nt++)
            #pragma unroll
            for (int r = 0; r < 4; r++) c[mt][nt][r] = 0.f;

    float4 pa0 = *(const float4*)(Ag + 0);
    float4 pa1 = *(const float4*)(Ag + 4);
    float4 pb0 = *(const float4*)(Bg + 0);
    float4 pb1 = *(const float4*)(Bg + 4);
    *(uint4*)&As[0][lrow][lcol]     = make_uint4(f2tf32(pa0.x), f2tf32(pa0.y), f2tf32(pa0.z), f2tf32(pa0.w));
    *(uint4*)&As[0][lrow][lcol + 4] = make_uint4(f2tf32(pa1.x), f2tf32(pa1.y), f2tf32(pa1.z), f2tf32(pa1.w));
    *(uint4*)&Bs[0][lrow][lcol]     = make_uint4(f2tf32(pb0.x), f2tf32(pb0.y), f2tf32(pb0.z), f2tf32(pb0.w));
    *(uint4*)&Bs[0][lrow][lcol + 4] = make_uint4(f2tf32(pb1.x), f2tf32(pb1.y), f2tf32(pb1.z), f2tf32(pb1.w));

    const int T = K >> 4;
    for (int t = 0; t < T; t++) {
        const int st = t & 1;
        if (t + 1 < T) {
            pa0 = *(const float4*)(Ag + (t+1)*16);     pa1 = *(const float4*)(Ag + (t+1)*16 + 4);
            pb0 = *(const float4*)(Bg + (t+1)*16);     pb1 = *(const float4*)(Bg + (t+1)*16 + 4);
        }
        __syncthreads();

        const uint32_t aa = a_base + st * STAGE;
        const uint32_t bb = b_base + st * STAGE;
        #pragma unroll
        for (int ks = 0; ks < 16; ks += 8) {
            uint32_t af[4][4], bf[4][2];
            #pragma unroll
            for (int mt = 0; mt < 4; mt++)
                LDSM4(af[mt][0], af[mt][1], af[mt][2], af[mt][3],
                      aa + (mt * 16 * 20 + ks) * 4);
            #pragma unroll
            for (int np = 0; np < 2; np++)
                LDSM4(bf[2*np][0], bf[2*np][1], bf[2*np+1][0], bf[2*np+1][1],
                      bb + (np * 16 * 20 + ks) * 4);
            #pragma unroll
            for (int mt = 0; mt < 4; mt++)
                #pragma unroll
                for (int nt = 0; nt < 4; nt++)
                    mma_tf32(c[mt][nt], af[mt][0], af[mt][1], af[mt][2], af[mt][3],
                             bf[nt][0], bf[nt][1]);
        }

        if (t + 1 < T) {
            const int so = st ^ 1;
            *(uint4*)&As[so][lrow][lcol]     = make_uint4(f2tf32(pa0.x), f2tf32(pa0.y), f2tf32(pa0.z), f2tf32(pa0.w));
            *(uint4*)&As[so][lrow][lcol + 4] = make_uint4(f2tf32(pa1.x), f2tf32(pa1.y), f2tf32(pa1.z), f2tf32(pa1.w));
            *(uint4*)&Bs[so][lrow][lcol]     = make_uint4(f2tf32(pb0.x), f2tf32(pb0.y), f2tf32(pb0.z), f2tf32(pb0.w));
            *(uint4*)&Bs[so][lrow][lcol + 4] = make_uint4(f2tf32(pb1.x), f2tf32(pb1.y), f2tf32(pb1.z), f2tf32(pb1.w));
        }
    }

    #pragma unroll
    for (int mt = 0; mt < 4; mt++) {
        int row = blockIdx.y * 128 + wm * 64 + mt * 16 + g;
        #pragma unroll
        for (int nt = 0; nt < 4; nt++) {
            int col = blockIdx.x * 128 + wn * 32 + nt * 8 + 2 * tg;
            *(float2*)(C + (long)row * N + col)       = make_float2(c[mt][nt][0], c[mt][nt][1]);
            *(float2*)(C + (long)(row + 8) * N + col) = make_float2(c[mt][nt][2], c[mt][nt][3]);
        }
    }
}

// ---------------- fused RoPE + RMSNorm + tf32 round (+optional scale) -------
__global__ void rope_rmsnorm(float* __restrict__ t, const float* __restrict__ cosb,
                             const float* __restrict__ sinb, const float* __restrict__ w,
                             int nheads, int nrows, float scale)
{
    int row  = blockIdx.x * 8 + (threadIdx.x >> 5);
    if (row >= nrows) return;
    int lane = threadIdx.x & 31;
    int s    = row / nheads;

    float* p = t + row * HD;
    float2 xv = ((float2*)p)[lane];
    float c  = cosb[s * (HD / 2) + lane];
    float sn = sinb[s * (HD / 2) + lane];
    float orr = xv.x * c - xv.y * sn;
    float oi  = xv.x * sn + xv.y * c;

    float ss = orr * orr + oi * oi;
    #pragma unroll
    for (int o = 16; o; o >>= 1) ss += __shfl_xor_sync(0xffffffffu, ss, o);
    float inv = rsqrtf(ss * (1.f / HD) + 1e-6f) * scale;

    float2 wv = ((const float2*)w)[lane];
    ((float2*)p)[lane] = make_float2(__uint_as_float(f2tf32(orr * inv * wv.x)),
                                     __uint_as_float(f2tf32(oi  * inv * wv.y)));
}

// ---------------- round V buffer to tf32 bits in place ----------------------
__global__ void round_tf32(float* __restrict__ p)
{
    int i = (blockIdx.x * 256 + threadIdx.x) * 4;
    float4 v = *(float4*)(p + i);
    v.x = __uint_as_float(f2tf32(v.x));
    v.y = __uint_as_float(f2tf32(v.y));
    v.z = __uint_as_float(f2tf32(v.z));
    v.w = __uint_as_float(f2tf32(v.w));
    *(float4*)(p + i) = v;
}

// ---------------- tensor-core flash attention, cp.async double-buffered -----
// Inputs q/k/v hold tf32 bit patterns (q pre-scaled by 1/sqrt(64)*log2e).
// Dyn smem: Ks[2][64][68] then Vs[2][64][72] (uint32 words). Q staged in Ks[1].
#define KS_STAGE 4352          // 64*68 words
#define VS_OFF   8704          // 2*KS_STAGE
#define VS_STAGE 4608          // 64*72 words
#define ATTN_SMEM ((VS_OFF + 2 * VS_STAGE) * 4)

__global__ void __launch_bounds__(128) attn_tc(const float* __restrict__ q,
                                               const float* __restrict__ k,
                                               const float* __restrict__ v,
                                               const float* __restrict__ gate,
                                               float* __restrict__ o)
{
    extern __shared__ uint32_t dsm[];
    const uint32_t sbase = smem_u32(dsm);

    const int qb   = 31 - blockIdx.x;
    const int h    = blockIdx.y;
    const int kvh  = h >> 2;
    const int tid  = threadIdx.x;
    const int lane = tid & 31;
    const int w    = tid >> 5;
    const int g    = lane >> 2;
    const int tg   = lane & 3;
    const int qi0  = qb * 64;

    const int lr = tid >> 1;             // 0..63
    const int lc = (tid & 1) * 32;       // 0 / 32

    // cp.async one K/V tile into stage st
    auto issue = [&](int kb, int st) {
        const float* kp = k + (((long)(kb * 64 + lr)) * NKV + kvh) * HD + lc;
        const float* vp = v + (((long)(kb * 64 + lr)) * NKV + kvh) * HD + lc;
        uint32_t kd = sbase + (st * KS_STAGE + lr * 68 + lc) * 4;
        uint32_t vd = sbase + (VS_OFF + st * VS_STAGE + lr * 72 + lc) * 4;
        #pragma unroll
        for (int u = 0; u < 8; u++) {
            CP16(kd + u * 16, kp + u * 4);
            CP16(vd + u * 16, vp + u * 4);
        }
    };

    issue(0, 0);
    CP_COMMIT();

    // stage Q bits into Ks stage 1 (already tf32 + scale)
    {
        const float* qp = q + (((long)(qi0 + lr)) * NH + h) * HD + lc;
        uint32_t* dst = dsm + KS_STAGE + lr * 68 + lc;
        #pragma unroll
        for (int u = 0; u < 8; u++)
            *(float4*)(dst + u * 4) = *(const float4*)(qp + u * 4);
    }
    __syncthreads();

    uint32_t qf[8][4];
    {
        const uint32_t qaddr = sbase + (KS_STAGE + (w * 16 + (lane & 15)) * 68 + ((lane & 16) ? 4 : 0)) * 4;
        #pragma unroll
        for (int ks = 0; ks < 8; ks++)
            LDSM4(qf[ks][0], qf[ks][1], qf[ks][2], qf[ks][3], qaddr + ks * 32);
    }
    __syncthreads();          // qf reads done before tile1 lands in Ks[1]

    if (qb >= 1) { issue(1, 1); CP_COMMIT(); }

    const uint32_t kpat = sbase + (((lane & 7) + ((lane & 16) >> 1)) * 68 + ((lane & 8) ? 4 : 0)) * 4;

    float oacc[8][4];
    #pragma unroll
    for (int nt = 0; nt < 8; nt++)
        #pragma unroll
        for (int r = 0; r < 4; r++) oacc[nt][r] = 0.f;
    float m0 = -1e30f, m1 = -1e30f, l0 = 0.f, l1 = 0.f;

    const int s0l  = (lane & ~3) + (tg >> 1);
    const int s2l  = s0l + 2;
    const bool odd = tg & 1;

    for (int kb = 0; kb <= qb; kb++) {
        const int st = kb & 1;
        if (kb < qb) { CP_WAIT(1); } else { CP_WAIT(0); }
        __syncthreads();                    // tile kb visible to all

        // ---- S = Q K^T ----
        float sc[8][4];
        #pragma unroll
        for (int nt = 0; nt < 8; nt++)
            #pragma unroll
            for (int r = 0; r < 4; r++) sc[nt][r] = 0.f;

        const uint32_t kst = kpat + st * (KS_STAGE * 4);
        #pragma unroll
        for (int ks = 0; ks < 8; ks++) {
            #pragma unroll
            for (int np = 0; np < 4; np++) {
                uint32_t b00, b01, b10, b11;
                LDSM4(b00, b01, b10, b11, kst + (np * 16 * 68 + ks * 8) * 4);
                mma_tf32(sc[2*np],   qf[ks][0], qf[ks][1], qf[ks][2], qf[ks][3], b00, b01);
                mma_tf32(sc[2*np+1], qf[ks][0], qf[ks][1], qf[ks][2], qf[ks][3], b10, b11);
            }
        }

        if (kb == qb) {
            int r0 = w*16 + g, r1 = r0 + 8;
            #pragma unroll
            for (int nt = 0; nt < 8; nt++) {
                int c0 = nt*8 + 2*tg, c1 = c0 + 1;
                if (c0 > r0) sc[nt][0] = -1e30f;
                if (c1 > r0) sc[nt][1] = -1e30f;
                if (c0 > r1) sc[nt][2] = -1e30f;
                if (c1 > r1) sc[nt][3] = -1e30f;
            }
        }

        // ---- online softmax (exp2 domain) ----
        float mt0 = -1e30f, mt1 = -1e30f;
        #pragma unroll
        for (int nt = 0; nt < 8; nt++) {
            mt0 = fmaxf(mt0, fmaxf(sc[nt][0], sc[nt][1]));
            mt1 = fmaxf(mt1, fmaxf(sc[nt][2], sc[nt][3]));
        }
        mt0 = fmaxf(mt0, __shfl_xor_sync(0xffffffffu, mt0, 1));
        mt0 = fmaxf(mt0, __shfl_xor_sync(0xffffffffu, mt0, 2));
        mt1 = fmaxf(mt1, __shfl_xor_sync(0xffffffffu, mt1, 1));
        mt1 = fmaxf(mt1, __shfl_xor_sync(0xffffffffu, mt1, 2));

        float mn0 = fmaxf(m0, mt0), mn1 = fmaxf(m1, mt1);
        float a0 = ex2(m0 - mn0), a1 = ex2(m1 - mn1);
        m0 = mn0; m1 = mn1;

        float rs0 = 0.f, rs1 = 0.f;
        uint32_t pr[8][4];
        #pragma unroll
        for (int nt = 0; nt < 8; nt++) {
            sc[nt][0] = ex2(sc[nt][0] - mn0);
            sc[nt][1] = ex2(sc[nt][1] - mn0);
            sc[nt][2] = ex2(sc[nt][2] - mn1);
            sc[nt][3] = ex2(sc[nt][3] - mn1);
            rs0 += sc[nt][0] + sc[nt][1];
            rs1 += sc[nt][2] + sc[nt][3];
            pr[nt][0] = f2tf32(sc[nt][0]);
            pr[nt][1] = f2tf32(sc[nt][1]);
            pr[nt][2] = f2tf32(sc[nt][2]);
            pr[nt][3] = f2tf32(sc[nt][3]);
        }
        rs0 += __shfl_xor_sync(0xffffffffu, rs0, 1);
        rs0 += __shfl_xor_sync(0xffffffffu, rs0, 2);
        rs1 += __shfl_xor_sync(0xffffffffu, rs1, 1);
        rs1 += __shfl_xor_sync(0xffffffffu, rs1, 2);
        l0 = l0 * a0 + rs0;
        l1 = l1 * a1 + rs1;

        #pragma unroll
        for (int nt = 0; nt < 8; nt++) {
            oacc[nt][0] *= a0; oacc[nt][1] *= a0;
            oacc[nt][2] *= a1; oacc[nt][3] *= a1;
        }

        // ---- O += P V (P via shfl; V bits already tf32) ----
        const uint32_t* Vst = dsm + VS_OFF + st * VS_STAGE;
        #pragma unroll
        for (int ks = 0; ks < 8; ks++) {
            uint32_t u00 = __shfl_sync(0xffffffffu, pr[ks][0], s0l);
            uint32_t u01 = __shfl_sync(0xffffffffu, pr[ks][1], s0l);
            uint32_t u20 = __shfl_sync(0xffffffffu, pr[ks][2], s0l);
            uint32_t u21 = __shfl_sync(0xffffffffu, pr[ks][3], s0l);
            uint32_t v00 = __shfl_sync(0xffffffffu, pr[ks][0], s2l);
            uint32_t v01 = __shfl_sync(0xffffffffu, pr[ks][1], s2l);
            uint32_t v20 = __shfl_sync(0xffffffffu, pr[ks][2], s2l);
            uint32_t v21 = __shfl_sync(0xffffffffu, pr[ks][3], s2l);
            uint32_t pa0 = odd ? u01 : u00;
            uint32_t pa1 = odd ? u21 : u20;
            uint32_t pa2 = odd ? v01 : v00;
            uint32_t pa3 = odd ? v21 : v20;
            #pragma unroll
            for (int nt = 0; nt < 8; nt++) {
                uint32_t b0 = Vst[(ks*8 + tg    ) * 72 + nt*8 + g];
                uint32_t b1 = Vst[(ks*8 + tg + 4) * 72 + nt*8 + g];
                mma_tf32(oacc[nt], pa0, pa1, pa2, pa3, b0, b1);
            }
        }

        __syncthreads();                    // stage st fully consumed
        if (kb + 2 <= qb) { issue(kb + 2, st); CP_COMMIT(); }
    }

    // ---- epilogue: normalize + fused sigmoid gate ----
    float invl0 = 1.f / l0, invl1 = 1.f / l1;
    int row0 = qi0 + w*16 + g;
    int row1 = row0 + 8;
    #pragma unroll
    for (int nt = 0; nt < 8; nt++) {
        int d = nt*8 + 2*tg;
        float2 ga = *(const float2*)(gate + (long)row0 * DIM + h * HD + d);
        float2 gb = *(const float2*)(gate + (long)row1 * DIM + h * HD + d);
        float2 o0, o1;
        o0.x = oacc[nt][0] * invl0 * (1.f / (1.f + __expf(-ga.x)));
        o0.y = oacc[nt][1] * invl0 * (1.f / (1.f + __expf(-ga.y)));
        o1.x = oacc[nt][2] * invl1 * (1.f / (1.f + __expf(-gb.x)));
        o1.y = oacc[nt][3] * invl1 * (1.f / (1.f + __expf(-gb.y)));
        *(float2*)(o + (long)row0 * DIM + h * HD + d) = o0;
        *(float2*)(o + (long)row1 * DIM + h * HD + d) = o1;
    }
}

// ---------------- launcher ---------------------------------------------------
extern "C" void kernel_launch(void* const* d_in, const int* in_sizes, int n_in,
                              void* d_out, int out_size)
{
    const float* x    = (const float*)d_in[0];
    const float* cosb = (const float*)d_in[1];
    const float* sinb = (const float*)d_in[2];
    const float* wq   = (const float*)d_in[3];
    const float* wk   = (const float*)d_in[4];
    const float* wv   = (const float*)d_in[5];
    const float* wo   = (const float*)d_in[6];
    const float* wg   = (const float*)d_in[7];
    const float* qn   = (const float*)d_in[8];
    const float* kn   = (const float*)d_in[9];
    float* out = (float*)d_out;

    float *qb, *kb, *vb, *gb, *ab;
    cudaGetSymbolAddress((void**)&qb, g_q);
    cudaGetSymbolAddress((void**)&kb, g_k);
    cudaGetSymbolAddress((void**)&vb, g_v);
    cudaGetSymbolAddress((void**)&gb, g_gate);
    cudaGetSymbolAddress((void**)&ab, g_att);

    static int attn_smem_set = 0;
    if (!attn_smem_set) {
        cudaFuncSetAttribute(attn_tc, cudaFuncAttributeMaxDynamicSharedMemorySize, ATTN_SMEM);
        attn_smem_set = 1;
    }

    // projections
    gemm_big<<<dim3(DIM / 128, SEQ / 128), 128>>>(x, wq, qb, SEQ, DIM, DIM);
    gemm_tf32<<<dim3((NKV * HD) / 128, SEQ / 128), 256>>>(x, wk, kb, SEQ, NKV * HD, DIM);
    gemm_tf32<<<dim3((NKV * HD) / 128, SEQ / 128), 256>>>(x, wv, vb, SEQ, NKV * HD, DIM);
    gemm_big<<<dim3(DIM / 128, SEQ / 128), 128>>>(x, wg, gb, SEQ, DIM, DIM);

    // RoPE + RMSNorm; Q gets softmax scale * log2e folded in; outputs tf32-rounded
    const float QSCALE = 0.125f * 1.44269504088896f;
    rope_rmsnorm<<<(SEQ * NH) / 8, 256>>>(qb, cosb, sinb, qn, NH, SEQ * NH, QSCALE);
    rope_rmsnorm<<<(SEQ * NKV) / 8, 256>>>(kb, cosb, sinb, kn, NKV, SEQ * NKV, 1.0f);
    round_tf32<<<(SEQ * NKV * HD) / 1024, 256>>>(vb);

    // attention + fused sigmoid gate
    attn_tc<<<dim3(SEQ / 64, NH), 128, ATTN_SMEM>>>(qb, kb, vb, gb, ab);

    // output projection
    gemm_big<<<dim3(DIM / 128, SEQ / 128), 128>>>(ab, wo, out, SEQ, DIM, DIM);
}